// round 13
// baseline (speedup 1.0000x reference)
#include <cuda_runtime.h>
#include <cuda_bf16.h>
#include <cstdint>

// Problem constants (fixed-shape problem)
#define T_DIM  128
#define B_DIM  2048
#define D_DIM  1024
#define AD_DIM 1024
#define KW     8
#define L_DIM  16
#define M_DIM  (L_DIM * B_DIM)   // 32768 gathered rows
#define NTILES (M_DIM / 128)     // 256 m-tiles

// GEMM tiling (fp8 e4m3 mma.sync m16n8k32; sm_100 base target)
#define GBM   128                // M rows per unit
#define GBN   256                // N cols per unit
#define GBK   64                 // K elements per stage (64 fp8 = 64 B/row)
#define NPASS (AD_DIM / GBN)     // 4
#define NSTG  (D_DIM / GBK)      // 16
#define NBUF  3                  // pipeline depth

#define NUNITS ((M_DIM / GBM) * NPASS)   // 1024 work units (m_tile, nt)
#define GRID_GEMM 148                    // persistent CTAs (1 per SM)
#define NTHREADS  544                    // 16 compute warps + 1 producer warp

#define ROWB    80               // padded row: 64 B data + 16 B pad
#define A_BYTES (GBM * ROWB)     // 10240
#define B_BYTES (GBN * ROWB)     // 20480
#define STG_BYTES (A_BYTES + B_BYTES)        // 30720
#define OFF_W2   0               // 256 floats
#define OFF_TILE 1024
#define GEMM_SMEM_TOTAL (OFF_TILE + NBUF * STG_BYTES)   // 93184

// named barrier for the 512 compute threads only
#define BAR_COMPUTE() asm volatile("bar.sync 1, 512;" ::: "memory")

// ---------------------------------------------------------------------------
// Scratch (device globals: no allocations allowed in kernel_launch)
// ---------------------------------------------------------------------------
__device__ uint8_t g_blkB8[(size_t)M_DIM * D_DIM];   // 32 MiB gathered rows, e4m3
__device__ uint8_t g_W1b8[(size_t)AD_DIM * D_DIM];   // 1 MiB  W1 in e4m3
__device__ float   g_s[M_DIM];                       // s[m] = W2 . tanh(W1 blk_m)
__device__ float   g_p[M_DIM];                       // batch-softmax of s
__device__ int     g_flag[NTILES];                   // per-m-tile ready counters (target 4)

// ---------------------------------------------------------------------------
// Helpers
// ---------------------------------------------------------------------------
__device__ __forceinline__ void window_of(int b, const int* __restrict__ off,
                                          const int* __restrict__ stc,
                                          const int* __restrict__ sep,
                                          int& start, int& end) {
    int o  = off[b];
    int sp = sep[b];          // sep_lst[b, 0]
    bool seg1 = (o <= sp);
    int s0 = o - KW;
    start = seg1 ? max(s0, 0) : max(s0, sp + 1);
    end   = seg1 ? min(o + KW, sp) : min(o + KW, stc[b]);
}

__device__ __forceinline__ uint32_t sptr(const void* p) {
    return (uint32_t)__cvta_generic_to_shared(p);
}
__device__ __forceinline__ void cp16(uint32_t dst, const void* src) {
    asm volatile("cp.async.cg.shared.global [%0], [%1], 16;" :: "r"(dst), "l"(src));
}
__device__ __forceinline__ void cp_commit() { asm volatile("cp.async.commit_group;"); }
template <int N> __device__ __forceinline__ void cp_wait() {
    asm volatile("cp.async.wait_group %0;" :: "n"(N));
}
__device__ __forceinline__ void ldsm4(uint32_t& r0, uint32_t& r1, uint32_t& r2, uint32_t& r3,
                                      uint32_t addr) {
    asm volatile("ldmatrix.sync.aligned.m8n8.x4.shared.b16 {%0,%1,%2,%3}, [%4];"
                 : "=r"(r0), "=r"(r1), "=r"(r2), "=r"(r3) : "r"(addr));
}
// fp8 e4m3 mma: m16n8k32, fragment layout = b16 m16n8k16 reinterpreted bytewise
__device__ __forceinline__ void mma16832(float* c, const uint32_t* a, uint32_t b0, uint32_t b1) {
    asm volatile(
        "mma.sync.aligned.m16n8k32.row.col.f32.e4m3.e4m3.f32 "
        "{%0,%1,%2,%3},{%4,%5,%6,%7},{%8,%9},{%0,%1,%2,%3};"
        : "+f"(c[0]), "+f"(c[1]), "+f"(c[2]), "+f"(c[3])
        : "r"(a[0]), "r"(a[1]), "r"(a[2]), "r"(a[3]), "r"(b0), "r"(b1));
}
// pack 2 floats -> e4m3x2 (lo = first/lower-k element)
__device__ __forceinline__ uint32_t fp8x2(float lo, float hi) {
    uint16_t p;
    asm("cvt.rn.satfinite.e4m3x2.f32 %0, %1, %2;" : "=h"(p) : "f"(hi), "f"(lo));
    return (uint32_t)p;
}
__device__ __forceinline__ float tanh_fast(float x) {
    float t;
    asm("tanh.approx.f32 %0, %1;" : "=f"(t) : "f"(x));
    return t;
}

// ---------------------------------------------------------------------------
// Kernel 1: W1 fp32 -> e4m3; also zeroes g_s and g_flag (runs before GEMM)
// ---------------------------------------------------------------------------
__global__ void convert_w1_kernel(const float* __restrict__ W1) {
    int gid = blockIdx.x * blockDim.x + threadIdx.x;     // 131072 threads
    if (gid < NTILES) g_flag[gid] = 0;
    if (gid < M_DIM)  g_s[gid] = 0.0f;
    int i = gid * 8;
    float4 v0 = *(const float4*)(W1 + i);
    float4 v1 = *(const float4*)(W1 + i + 4);
    uint32_t p0 = fp8x2(v0.x, v0.y), p1 = fp8x2(v0.z, v0.w);
    uint32_t p2 = fp8x2(v1.x, v1.y), p3 = fp8x2(v1.z, v1.w);
    uint64_t o = (uint64_t)(p0 | (p1 << 16)) | ((uint64_t)(p2 | (p3 << 16)) << 32);
    *(uint64_t*)&g_W1b8[i] = o;
}

// ---------------------------------------------------------------------------
// Producer-warp gather: rows [r0, r0+nrows) of m-tile t, by one warp.
// Per row: 8 coalesced float4 loads per lane-group, fp8 convert, 4B stores.
// ---------------------------------------------------------------------------
__device__ void produce_rows(int t, int r0, int nrows, int lane,
                             const float* __restrict__ h,
                             const int* __restrict__ off,
                             const int* __restrict__ stc,
                             const int* __restrict__ sep) {
    for (int r = r0; r < r0 + nrows; ++r) {
        int m = t * 128 + r;
        int b = m & (B_DIM - 1);
        int l = m >> 11;
        int start, end;
        window_of(b, off, stc, sep, start, end);
        int idx = min(max(start + l, 0), T_DIM - 1);
        const float4* src = (const float4*)(h + ((size_t)idx * B_DIM + b) * D_DIM);
        uint32_t* dst = (uint32_t*)&g_blkB8[(size_t)m * D_DIM];
        #pragma unroll
        for (int j = 0; j < 8; ++j) {
            float4 v = src[lane + 32 * j];
            dst[lane + 32 * j] = fp8x2(v.x, v.y) | (fp8x2(v.z, v.w) << 16);
        }
    }
}

// ---------------------------------------------------------------------------
// Kernel 2: persistent GEMM with in-kernel producer warp.
// 148 CTAs x 544 threads: warps 0-15 compute (BM=128 x BN=256, fp8 mma),
// warp 16 gathers m-tiles (flag counters, target 4 per tile).
// ---------------------------------------------------------------------------
extern __shared__ char dyn_smem[];

__device__ __forceinline__ void load_stage(uint32_t tile_base, int slot, int k0,
                                           int m_base, int nbase, int tid) {
    uint32_t abase = tile_base + slot * STG_BYTES;
    uint32_t bbase = abase + A_BYTES;
    // A: 128 rows x 4 x16B chunks = 512 chunks, 1 per compute thread
    {
        int row = tid >> 2, c = tid & 3;
        cp16(abase + row * ROWB + c * 16,
             &g_blkB8[(size_t)(m_base + row) * D_DIM + k0 + c * 16]);
    }
    // B: 256 rows x 4 chunks = 1024 chunks, 2 per compute thread
    #pragma unroll
    for (int i = 0; i < 2; ++i) {
        int ch  = tid + i * 512;
        int row = ch >> 2, c = ch & 3;
        cp16(bbase + row * ROWB + c * 16,
             &g_W1b8[(size_t)(nbase + row) * D_DIM + k0 + c * 16]);
    }
}

__global__ void __launch_bounds__(NTHREADS, 1) gemm_s_kernel(
        const float* __restrict__ h,
        const int* __restrict__ off,
        const int* __restrict__ stc,
        const int* __restrict__ sep,
        const float* __restrict__ W2) {
    const uint32_t smem_base = sptr(dyn_smem);
    const uint32_t tile_base = smem_base + OFF_TILE;
    float* sW2 = (float*)(dyn_smem + OFF_W2);

    const int tid  = threadIdx.x;
    const int lane = tid & 31;
    const int cta  = blockIdx.x;

    // ---------------- producer warp (tid 512..543): never waits -------------
    if (tid >= 512) {
        // Wave A: tiles 0..36, 4 producers each (32 rows apiece) — phase-0 set
        int tA = cta % 37, qA = cta / 37;
        produce_rows(tA, qA * 32, 32, lane, h, off, stc, sep);
        __syncwarp();
        if (lane == 0) { __threadfence(); atomicAdd(&g_flag[tA], 1); }
        // Wave B: tile 37+cta (needed from phase 1 on)
        int tB = 37 + cta;
        produce_rows(tB, 0, 128, lane, h, off, stc, sep);
        __syncwarp();
        if (lane == 0) { __threadfence(); atomicAdd(&g_flag[tB], 4); }
        // Wave C: tiles 185..255 (needed from phase 5 on)
        if (cta < NTILES - 185) {
            int tC = 185 + cta;
            produce_rows(tC, 0, 128, lane, h, off, stc, sep);
            __syncwarp();
            if (lane == 0) { __threadfence(); atomicAdd(&g_flag[tC], 4); }
        }
        return;
    }

    // ---------------- compute warps 0..15 ----------------------------------
    const int wid = tid >> 5;
    const int warp_m = wid & 3;          // 4 -> 32 rows each
    const int warp_n = wid >> 2;         // 4 -> 64 cols each
    const int rm = warp_m * 32;
    const int cn = warp_n * 64;

    // ldmatrix lane geometry (verified)
    const int mat = lane >> 3;
    const int lq  = lane & 7;
    const int rowA0    = rm + (mat & 1) * 8 + lq;       // + fm*16
    const int colAbase = (mat >> 1) * 8;                // b16 units; + ks*16
    const int colBbase = (mat & 1) * 8;                 // b16 units; + ks*16

    for (int u = cta; u < NUNITS; u += GRID_GEMM) {
        const int m_base = (u >> 2) * GBM;
        const int nbase  = (u & 3) * GBN;

        // wait for this unit's m-tile (threadFenceReduction pattern; R11-proven)
        if (tid == 0) {
            while (atomicAdd(&g_flag[u >> 2], 0) < 4) { }
        }
        BAR_COMPUTE();                   // also: prev unit done with tiles/sW2
        if (tid < GBN) sW2[tid] = W2[nbase + tid];

        float acc[2][8][4];
        #pragma unroll
        for (int fm = 0; fm < 2; fm++)
            #pragma unroll
            for (int j = 0; j < 8; j++)
                #pragma unroll
                for (int r = 0; r < 4; r++) acc[fm][j][r] = 0.0f;

        // prologue: stages 0,1
        load_stage(tile_base, 0, 0, m_base, nbase, tid);
        cp_commit();
        load_stage(tile_base, 1, GBK, m_base, nbase, tid);
        cp_commit();

        int slot = 0;        // compute slot (s % 3)
        int lslot = 2;       // load slot ((s+2) % 3)
        for (int s = 0; s < NSTG; ++s) {
            if (s == NSTG - 1) { cp_wait<0>(); } else { cp_wait<1>(); }
            BAR_COMPUTE();               // stage s visible; all done with s-1
            if (s + 2 < NSTG) {
                load_stage(tile_base, lslot, (s + 2) * GBK, m_base, nbase, tid);
                cp_commit();
            }

            const uint32_t abase = tile_base + slot * STG_BYTES;
            const uint32_t bbase = abase + A_BYTES;
            #pragma unroll
            for (int ks = 0; ks < 2; ks++) {     // 2 x k32 per 64-elem stage
                uint32_t a[2][4];
                #pragma unroll
                for (int fm = 0; fm < 2; fm++)
                    ldsm4(a[fm][0], a[fm][1], a[fm][2], a[fm][3],
                          abase + (rowA0 + fm * 16) * ROWB + (colAbase + ks * 16) * 2);
                uint32_t bf[8][2];
                #pragma unroll
                for (int jp = 0; jp < 4; jp++) {
                    uint32_t b0, b1, b2, b3;
                    int rowB = cn + 8 * (2 * jp + (mat >> 1)) + lq;
                    ldsm4(b0, b1, b2, b3,
                          bbase + rowB * ROWB + (colBbase + ks * 16) * 2);
                    bf[2 * jp][0] = b0;  bf[2 * jp][1] = b1;
                    bf[2 * jp + 1][0] = b2;  bf[2 * jp + 1][1] = b3;
                }
                #pragma unroll
                for (int fm = 0; fm < 2; fm++)
                    #pragma unroll
                    for (int j = 0; j < 8; j++)
                        mma16832(acc[fm][j], a[fm], bf[j][0], bf[j][1]);
            }
            if (++slot == NBUF) slot = 0;
            if (++lslot == NBUF) lslot = 0;
        }

        // epilogue: g_s[row] += W2[a] * tanh(acc)  (global red.add)
        float p[4] = {0.f, 0.f, 0.f, 0.f};
        #pragma unroll
        for (int fm = 0; fm < 2; fm++)
            #pragma unroll
            for (int j = 0; j < 8; j++)
                #pragma unroll
                for (int r = 0; r < 4; r++) {
                    int col_local = cn + 8 * j + 2 * (lane & 3) + (r & 1);
                    p[fm * 2 + (r >> 1)] += sW2[col_local] * tanh_fast(acc[fm][j][r]);
                }
        #pragma unroll
        for (int i = 0; i < 4; i++) {
            p[i] += __shfl_xor_sync(0xffffffff, p[i], 1);
            p[i] += __shfl_xor_sync(0xffffffff, p[i], 2);
        }
        if ((lane & 3) == 0) {
            int r0 = m_base + rm + (lane >> 2);
            atomicAdd(&g_s[r0],      p[0]);
            atomicAdd(&g_s[r0 + 8],  p[1]);
            atomicAdd(&g_s[r0 + 16], p[2]);
            atomicAdd(&g_s[r0 + 24], p[3]);
        }
    }
}

// ---------------------------------------------------------------------------
// Kernel 3: softmax over batch axis per l; invalid entries use s = 0
// (matches reference: blk=0 for invalid -> s = W2.tanh(0) = 0)
// ---------------------------------------------------------------------------
__global__ void softmax_b_kernel(const int* __restrict__ off,
                                 const int* __restrict__ stc,
                                 const int* __restrict__ sep) {
    const int l = blockIdx.x;
    const int tid = threadIdx.x;                  // 256 threads, 8 b's each
    __shared__ float red[256];

    float v[8];
    float mx = -1e30f;
    #pragma unroll
    for (int i = 0; i < 8; i++) {
        int b = tid + i * 256;
        int start, end;
        window_of(b, off, stc, sep, start, end);
        bool valid = (start + l) < end;
        v[i] = valid ? g_s[l * B_DIM + b] : 0.0f;
        mx = fmaxf(mx, v[i]);
    }
    red[tid] = mx; __syncthreads();
    for (int s = 128; s > 0; s >>= 1) {
        if (tid < s) red[tid] = fmaxf(red[tid], red[tid + s]);
        __syncthreads();
    }
    mx = red[0]; __syncthreads();

    float e[8]; float sum = 0.0f;
    #pragma unroll
    for (int i = 0; i < 8; i++) { e[i] = expf(v[i] - mx); sum += e[i]; }
    red[tid] = sum; __syncthreads();
    for (int s = 128; s > 0; s >>= 1) {
        if (tid < s) red[tid] += red[tid + s];
        __syncthreads();
    }
    sum = red[0];

    float inv = 1.0f / sum;
    #pragma unroll
    for (int i = 0; i < 8; i++) {
        int b = tid + i * 256;
        g_p[l * B_DIM + b] = e[i] * inv;
    }
}

// ---------------------------------------------------------------------------
// Kernel 4: per-b masked softmax over L + fp32 weighted sum of h_context rows.
// grid (B, 2): each block covers 512 columns (one float4 slot per thread).
// ---------------------------------------------------------------------------
__global__ void finalize_kernel(const float* __restrict__ h,
                                const int* __restrict__ off,
                                const int* __restrict__ stc,
                                const int* __restrict__ sep,
                                float* __restrict__ out) {
    const int b = blockIdx.x;
    int start, end;
    window_of(b, off, stc, sep, start, end);

    float logit[L_DIM];
    float mx = -INFINITY;
    #pragma unroll
    for (int l = 0; l < L_DIM; l++) {
        bool valid = (start + l) < end;
        logit[l] = valid ? g_p[l * B_DIM + b] : -INFINITY;
        mx = fmaxf(mx, logit[l]);
    }
    float w[L_DIM]; float sum = 0.0f;
    #pragma unroll
    for (int l = 0; l < L_DIM; l++) { w[l] = expf(logit[l] - mx); sum += w[l]; }
    float inv = 1.0f / sum;

    const int col4 = blockIdx.y * 128 + threadIdx.x;   // float4 slot (0..255)
    float4 a = make_float4(0.f, 0.f, 0.f, 0.f);
    #pragma unroll
    for (int l = 0; l < L_DIM; l++) {
        int idx = min(max(start + l, 0), T_DIM - 1);
        float wl = (start + l < end) ? w[l] * inv : 0.0f;
        float4 x = ((const float4*)(h + ((size_t)idx * B_DIM + b) * D_DIM))[col4];
        a.x += wl * x.x; a.y += wl * x.y; a.z += wl * x.z; a.w += wl * x.w;
    }
    ((float4*)(out + (size_t)b * D_DIM))[col4] = a;
}

// ---------------------------------------------------------------------------
// Launch
// inputs (metadata order): h_context f32, offsets i32, stc_lens i32,
// sep_lst i32, no_local i32 (unused), W1 f32, W2 f32 -> out f32 (B,1,D)
// ---------------------------------------------------------------------------
extern "C" void kernel_launch(void* const* d_in, const int* in_sizes, int n_in,
                              void* d_out, int out_size) {
    (void)in_sizes; (void)n_in; (void)out_size;
    const float* h   = (const float*)d_in[0];
    const int*   off = (const int*)d_in[1];
    const int*   stc = (const int*)d_in[2];
    const int*   sep = (const int*)d_in[3];
    const float* W1  = (const float*)d_in[5];
    const float* W2  = (const float*)d_in[6];
    float*       out = (float*)d_out;

    static int smem_set = 0;
    if (!smem_set) {
        cudaFuncSetAttribute(gemm_s_kernel,
                             cudaFuncAttributeMaxDynamicSharedMemorySize, GEMM_SMEM_TOTAL);
        smem_set = 1;
    }

    convert_w1_kernel<<<(AD_DIM * D_DIM) / (256 * 8), 256>>>(W1);
    gemm_s_kernel<<<GRID_GEMM, NTHREADS, GEMM_SMEM_TOTAL>>>(h, off, stc, sep, W2);
    softmax_b_kernel<<<L_DIM, 256>>>(off, stc, sep);
    finalize_kernel<<<dim3(B_DIM, 2), 128>>>(h, off, stc, sep, out);
}

// round 14
// speedup vs baseline: 1.3777x; 1.3777x over previous
#include <cuda_runtime.h>
#include <cuda_bf16.h>
#include <cstdint>

// Problem constants (fixed-shape problem)
#define T_DIM  128
#define B_DIM  2048
#define D_DIM  1024
#define AD_DIM 1024
#define KW     8
#define L_DIM  16
#define M_DIM  (L_DIM * B_DIM)   // 32768 gathered rows

// GEMM tiling (fp8 e4m3 mma.sync m16n8k32; sm_100 base target)
#define GBM   128                // M rows per unit
#define GBN   256                // N cols per unit
#define GBK   64                 // K elements per stage (64 fp8 = 64 B/row)
#define NPASS (AD_DIM / GBN)     // 4
#define NSTG  (D_DIM / GBK)      // 16
#define NBUF  3                  // pipeline depth

#define NUNITS ((M_DIM / GBM) * NPASS)   // 1024 work units (m_tile, nt)
#define GRID_GEMM 148                    // persistent CTAs (1 per SM)

#define ROWB    80               // padded row: 64 B data + 16 B pad
#define A_BYTES (GBM * ROWB)     // 10240
#define B_BYTES (GBN * ROWB)     // 20480
#define STG_BYTES (A_BYTES + B_BYTES)        // 30720
#define OFF_W2   0               // 256 floats
#define OFF_TILE 1024
#define GEMM_SMEM_TOTAL (OFF_TILE + NBUF * STG_BYTES)   // 93184

// ---------------------------------------------------------------------------
// Scratch (device globals: no allocations allowed in kernel_launch)
// ---------------------------------------------------------------------------
__device__ uint8_t g_blkB8[(size_t)M_DIM * D_DIM];   // 32 MiB gathered rows, e4m3
__device__ uint8_t g_W1b8[(size_t)AD_DIM * D_DIM];   // 1 MiB  W1 in e4m3
__device__ float   g_s[M_DIM];                       // s[m] = W2 . tanh(W1 blk_m)
__device__ float   g_p[M_DIM];                       // batch-softmax of s

// ---------------------------------------------------------------------------
// Helpers
// ---------------------------------------------------------------------------
__device__ __forceinline__ void window_of(int b, const int* __restrict__ off,
                                          const int* __restrict__ stc,
                                          const int* __restrict__ sep,
                                          int& start, int& end) {
    int o  = off[b];
    int sp = sep[b];          // sep_lst[b, 0]
    bool seg1 = (o <= sp);
    int s0 = o - KW;
    start = seg1 ? max(s0, 0) : max(s0, sp + 1);
    end   = seg1 ? min(o + KW, sp) : min(o + KW, stc[b]);
}

__device__ __forceinline__ uint32_t sptr(const void* p) {
    return (uint32_t)__cvta_generic_to_shared(p);
}
__device__ __forceinline__ void cp16(uint32_t dst, const void* src) {
    asm volatile("cp.async.cg.shared.global [%0], [%1], 16;" :: "r"(dst), "l"(src));
}
__device__ __forceinline__ void cp_commit() { asm volatile("cp.async.commit_group;"); }
template <int N> __device__ __forceinline__ void cp_wait() {
    asm volatile("cp.async.wait_group %0;" :: "n"(N));
}
__device__ __forceinline__ void ldsm4(uint32_t& r0, uint32_t& r1, uint32_t& r2, uint32_t& r3,
                                      uint32_t addr) {
    asm volatile("ldmatrix.sync.aligned.m8n8.x4.shared.b16 {%0,%1,%2,%3}, [%4];"
                 : "=r"(r0), "=r"(r1), "=r"(r2), "=r"(r3) : "r"(addr));
}
// fp8 e4m3 mma: m16n8k32, fragment layout = b16 m16n8k16 reinterpreted bytewise
__device__ __forceinline__ void mma16832(float* c, const uint32_t* a, uint32_t b0, uint32_t b1) {
    asm volatile(
        "mma.sync.aligned.m16n8k32.row.col.f32.e4m3.e4m3.f32 "
        "{%0,%1,%2,%3},{%4,%5,%6,%7},{%8,%9},{%0,%1,%2,%3};"
        : "+f"(c[0]), "+f"(c[1]), "+f"(c[2]), "+f"(c[3])
        : "r"(a[0]), "r"(a[1]), "r"(a[2]), "r"(a[3]), "r"(b0), "r"(b1));
}
// pack 2 floats -> e4m3x2 (lo = first/lower-k element)
__device__ __forceinline__ uint32_t fp8x2(float lo, float hi) {
    uint16_t p;
    asm("cvt.rn.satfinite.e4m3x2.f32 %0, %1, %2;" : "=h"(p) : "f"(hi), "f"(lo));
    return (uint32_t)p;
}
__device__ __forceinline__ float tanh_fast(float x) {
    float t;
    asm("tanh.approx.f32 %0, %1;" : "=f"(t) : "f"(x));
    return t;
}

// ---------------------------------------------------------------------------
// Kernel 1: W1 fp32 -> e4m3
// ---------------------------------------------------------------------------
__global__ void convert_w1_kernel(const float* __restrict__ W1) {
    int i = (blockIdx.x * blockDim.x + threadIdx.x) * 8;   // grid covers 1M elems
    float4 v0 = *(const float4*)(W1 + i);
    float4 v1 = *(const float4*)(W1 + i + 4);
    uint32_t p0 = fp8x2(v0.x, v0.y), p1 = fp8x2(v0.z, v0.w);
    uint32_t p2 = fp8x2(v1.x, v1.y), p3 = fp8x2(v1.z, v1.w);
    uint64_t o = (uint64_t)(p0 | (p1 << 16)) | ((uint64_t)(p2 | (p3 << 16)) << 32);
    *(uint64_t*)&g_W1b8[i] = o;
}

// ---------------------------------------------------------------------------
// Kernel 2: gather window rows -> e4m3 blk  (m = l*B + b); also zeros g_s[m]
// Invalid rows use a clipped index; their s is masked later and their final
// weight is exactly 0, so the garbage never propagates.
// ---------------------------------------------------------------------------
__global__ void gather_kernel(const float* __restrict__ h,
                              const int* __restrict__ off,
                              const int* __restrict__ stc,
                              const int* __restrict__ sep) {
    int m = blockIdx.x;
    if (threadIdx.x == 0) g_s[m] = 0.0f;    // GEMM accumulates into g_s
    int b = m & (B_DIM - 1);
    int l = m >> 11;
    int start, end;
    window_of(b, off, stc, sep, start, end);
    int idx = start + l;
    idx = min(max(idx, 0), T_DIM - 1);

    const float4* src = (const float4*)(h + ((size_t)idx * B_DIM + b) * D_DIM);
    int t = threadIdx.x;                    // 128 threads, 8 floats each
    float4 v0 = src[t * 2];
    float4 v1 = src[t * 2 + 1];
    uint32_t p0 = fp8x2(v0.x, v0.y), p1 = fp8x2(v0.z, v0.w);
    uint32_t p2 = fp8x2(v1.x, v1.y), p3 = fp8x2(v1.z, v1.w);
    uint64_t o = (uint64_t)(p0 | (p1 << 16)) | ((uint64_t)(p2 | (p3 << 16)) << 32);
    *(uint64_t*)&g_blkB8[(size_t)m * D_DIM + t * 8] = o;
}

// ---------------------------------------------------------------------------
// Kernel 3: persistent GEMM  pre[m,a] = blk[m,:] . W1[a,:]  (e4m3 -> fp32)
// fused epilogue: g_s[m] += sum_a W2[a] * tanh(pre[m,a])  (global red.add)
// 148 persistent CTAs x 512 threads; static partition of 1024 (m_tile, nt)
// units. Next unit's stage-0/1 cp.async are issued BEFORE the epilogue so
// their DRAM latency hides under the tanh/reduction work.
// ---------------------------------------------------------------------------
extern __shared__ char dyn_smem[];

__device__ __forceinline__ void load_stage(uint32_t tile_base, int slot, int k0,
                                           int m_base, int nbase, int tid) {
    uint32_t abase = tile_base + slot * STG_BYTES;
    uint32_t bbase = abase + A_BYTES;
    // A: 128 rows x 4 x16B chunks = 512 chunks, 1 per thread
    {
        int row = tid >> 2, c = tid & 3;
        cp16(abase + row * ROWB + c * 16,
             &g_blkB8[(size_t)(m_base + row) * D_DIM + k0 + c * 16]);
    }
    // B: 256 rows x 4 chunks = 1024 chunks, 2 per thread
    #pragma unroll
    for (int i = 0; i < 2; ++i) {
        int ch  = tid + i * 512;
        int row = ch >> 2, c = ch & 3;
        cp16(bbase + row * ROWB + c * 16,
             &g_W1b8[(size_t)(nbase + row) * D_DIM + k0 + c * 16]);
    }
}

__global__ void __launch_bounds__(512, 1) gemm_s_kernel(const float* __restrict__ W2) {
    const uint32_t smem_base = sptr(dyn_smem);
    const uint32_t tile_base = smem_base + OFF_TILE;
    float* sW2 = (float*)(dyn_smem + OFF_W2);

    const int tid  = threadIdx.x;
    const int wid  = tid >> 5;
    const int lane = tid & 31;

    const int warp_m = wid & 3;          // 4 -> 32 rows each
    const int warp_n = wid >> 2;         // 4 -> 64 cols each
    const int rm = warp_m * 32;
    const int cn = warp_n * 64;

    // ldmatrix lane geometry (verified)
    const int mat = lane >> 3;
    const int lq  = lane & 7;
    const int rowA0    = rm + (mat & 1) * 8 + lq;       // + fm*16
    const int colAbase = (mat >> 1) * 8;                // b16 units; + ks*16
    const int colBbase = (mat & 1) * 8;                 // b16 units; + ks*16

    // pre-loop prologue: stages 0,1 of the first unit
    {
        const int u0 = blockIdx.x;
        const int mb = (u0 >> 2) * GBM, nb = (u0 & 3) * GBN;
        load_stage(tile_base, 0, 0, mb, nb, tid);
        cp_commit();
        load_stage(tile_base, 1, GBK, mb, nb, tid);
        cp_commit();
    }

    for (int u = blockIdx.x; u < NUNITS; u += GRID_GEMM) {
        const int m_base = (u >> 2) * GBM;
        const int nbase  = (u & 3) * GBN;

        float acc[2][8][4];
        #pragma unroll
        for (int fm = 0; fm < 2; fm++)
            #pragma unroll
            for (int j = 0; j < 8; j++)
                #pragma unroll
                for (int r = 0; r < 4; r++) acc[fm][j][r] = 0.0f;

        int slot = 0;        // compute slot (s % 3)
        int lslot = 2;       // load slot ((s+2) % 3)
        for (int s = 0; s < NSTG; ++s) {
            if (s == NSTG - 1) { cp_wait<0>(); } else { cp_wait<1>(); }
            __syncthreads();             // stage s visible; all done with s-1;
                                         // at s==0 also: prev epilogue done with sW2
            if (s == 0 && tid < GBN) sW2[tid] = W2[nbase + tid];
            if (s + 2 < NSTG) {
                load_stage(tile_base, lslot, (s + 2) * GBK, m_base, nbase, tid);
                cp_commit();
            }

            const uint32_t abase = tile_base + slot * STG_BYTES;
            const uint32_t bbase = abase + A_BYTES;
            #pragma unroll
            for (int ks = 0; ks < 2; ks++) {     // 2 x k32 per 64-elem stage
                uint32_t a[2][4];
                #pragma unroll
                for (int fm = 0; fm < 2; fm++)
                    ldsm4(a[fm][0], a[fm][1], a[fm][2], a[fm][3],
                          abase + (rowA0 + fm * 16) * ROWB + (colAbase + ks * 16) * 2);
                uint32_t bf[8][2];
                #pragma unroll
                for (int jp = 0; jp < 4; jp++) {
                    uint32_t b0, b1, b2, b3;
                    int rowB = cn + 8 * (2 * jp + (mat >> 1)) + lq;
                    ldsm4(b0, b1, b2, b3,
                          bbase + rowB * ROWB + (colBbase + ks * 16) * 2);
                    bf[2 * jp][0] = b0;  bf[2 * jp][1] = b1;
                    bf[2 * jp + 1][0] = b2;  bf[2 * jp + 1][1] = b3;
                }
                #pragma unroll
                for (int fm = 0; fm < 2; fm++)
                    #pragma unroll
                    for (int j = 0; j < 8; j++)
                        mma16832(acc[fm][j], a[fm], bf[j][0], bf[j][1]);
            }
            if (++slot == NBUF) slot = 0;
            if (++lslot == NBUF) lslot = 0;
        }

        // all warps finished their last-stage ldsm -> slots 0,1 reusable
        __syncthreads();
        if (u + GRID_GEMM < NUNITS) {    // prefetch next unit under the epilogue
            const int un = u + GRID_GEMM;
            const int mb = (un >> 2) * GBM, nb = (un & 3) * GBN;
            load_stage(tile_base, 0, 0, mb, nb, tid);
            cp_commit();
            load_stage(tile_base, 1, GBK, mb, nb, tid);
            cp_commit();
        }

        // epilogue: g_s[row] += W2[a] * tanh(acc)  (global red.add)
        float p[4] = {0.f, 0.f, 0.f, 0.f};
        #pragma unroll
        for (int fm = 0; fm < 2; fm++)
            #pragma unroll
            for (int j = 0; j < 8; j++)
                #pragma unroll
                for (int r = 0; r < 4; r++) {
                    int col_local = cn + 8 * j + 2 * (lane & 3) + (r & 1);
                    p[fm * 2 + (r >> 1)] += sW2[col_local] * tanh_fast(acc[fm][j][r]);
                }
        #pragma unroll
        for (int i = 0; i < 4; i++) {
            p[i] += __shfl_xor_sync(0xffffffff, p[i], 1);
            p[i] += __shfl_xor_sync(0xffffffff, p[i], 2);
        }
        if ((lane & 3) == 0) {
            int r0 = m_base + rm + (lane >> 2);
            atomicAdd(&g_s[r0],      p[0]);
            atomicAdd(&g_s[r0 + 8],  p[1]);
            atomicAdd(&g_s[r0 + 16], p[2]);
            atomicAdd(&g_s[r0 + 24], p[3]);
        }
    }
}

// ---------------------------------------------------------------------------
// Kernel 4: softmax over batch axis per l; invalid entries use s = 0
// (matches reference: blk=0 for invalid -> s = W2.tanh(0) = 0)
// ---------------------------------------------------------------------------
__global__ void softmax_b_kernel(const int* __restrict__ off,
                                 const int* __restrict__ stc,
                                 const int* __restrict__ sep) {
    const int l = blockIdx.x;
    const int tid = threadIdx.x;                  // 256 threads, 8 b's each
    __shared__ float red[256];

    float v[8];
    float mx = -1e30f;
    #pragma unroll
    for (int i = 0; i < 8; i++) {
        int b = tid + i * 256;
        int start, end;
        window_of(b, off, stc, sep, start, end);
        bool valid = (start + l) < end;
        v[i] = valid ? g_s[l * B_DIM + b] : 0.0f;
        mx = fmaxf(mx, v[i]);
    }
    red[tid] = mx; __syncthreads();
    for (int s = 128; s > 0; s >>= 1) {
        if (tid < s) red[tid] = fmaxf(red[tid], red[tid + s]);
        __syncthreads();
    }
    mx = red[0]; __syncthreads();

    float e[8]; float sum = 0.0f;
    #pragma unroll
    for (int i = 0; i < 8; i++) { e[i] = expf(v[i] - mx); sum += e[i]; }
    red[tid] = sum; __syncthreads();
    for (int s = 128; s > 0; s >>= 1) {
        if (tid < s) red[tid] += red[tid + s];
        __syncthreads();
    }
    sum = red[0];

    float inv = 1.0f / sum;
    #pragma unroll
    for (int i = 0; i < 8; i++) {
        int b = tid + i * 256;
        g_p[l * B_DIM + b] = e[i] * inv;
    }
}

// ---------------------------------------------------------------------------
// Kernel 5: per-b masked softmax over L + fp32 weighted sum of h_context rows.
// grid (B, 2): each block covers 512 columns (one float4 slot per thread).
// ---------------------------------------------------------------------------
__global__ void finalize_kernel(const float* __restrict__ h,
                                const int* __restrict__ off,
                                const int* __restrict__ stc,
                                const int* __restrict__ sep,
                                float* __restrict__ out) {
    const int b = blockIdx.x;
    int start, end;
    window_of(b, off, stc, sep, start, end);

    float logit[L_DIM];
    float mx = -INFINITY;
    #pragma unroll
    for (int l = 0; l < L_DIM; l++) {
        bool valid = (start + l) < end;
        logit[l] = valid ? g_p[l * B_DIM + b] : -INFINITY;
        mx = fmaxf(mx, logit[l]);
    }
    float w[L_DIM]; float sum = 0.0f;
    #pragma unroll
    for (int l = 0; l < L_DIM; l++) { w[l] = expf(logit[l] - mx); sum += w[l]; }
    float inv = 1.0f / sum;

    const int col4 = blockIdx.y * 128 + threadIdx.x;   // float4 slot (0..255)
    float4 a = make_float4(0.f, 0.f, 0.f, 0.f);
    #pragma unroll
    for (int l = 0; l < L_DIM; l++) {
        int idx = min(max(start + l, 0), T_DIM - 1);
        float wl = (start + l < end) ? w[l] * inv : 0.0f;
        float4 x = ((const float4*)(h + ((size_t)idx * B_DIM + b) * D_DIM))[col4];
        a.x += wl * x.x; a.y += wl * x.y; a.z += wl * x.z; a.w += wl * x.w;
    }
    ((float4*)(out + (size_t)b * D_DIM))[col4] = a;
}

// ---------------------------------------------------------------------------
// Launch
// inputs (metadata order): h_context f32, offsets i32, stc_lens i32,
// sep_lst i32, no_local i32 (unused), W1 f32, W2 f32 -> out f32 (B,1,D)
// ---------------------------------------------------------------------------
extern "C" void kernel_launch(void* const* d_in, const int* in_sizes, int n_in,
                              void* d_out, int out_size) {
    (void)in_sizes; (void)n_in; (void)out_size;
    const float* h   = (const float*)d_in[0];
    const int*   off = (const int*)d_in[1];
    const int*   stc = (const int*)d_in[2];
    const int*   sep = (const int*)d_in[3];
    const float* W1  = (const float*)d_in[5];
    const float* W2  = (const float*)d_in[6];
    float*       out = (float*)d_out;

    static int smem_set = 0;
    if (!smem_set) {
        cudaFuncSetAttribute(gemm_s_kernel,
                             cudaFuncAttributeMaxDynamicSharedMemorySize, GEMM_SMEM_TOTAL);
        smem_set = 1;
    }

    convert_w1_kernel<<<(AD_DIM * D_DIM) / (256 * 8), 256>>>(W1);
    gather_kernel<<<M_DIM, 128>>>(h, off, stc, sep);
    gemm_s_kernel<<<GRID_GEMM, 512, GEMM_SMEM_TOTAL>>>(W2);
    softmax_b_kernel<<<L_DIM, 256>>>(off, stc, sep);
    finalize_kernel<<<dim3(B_DIM, 2), 128>>>(h, off, stc, sep, out);
}

// round 15
// speedup vs baseline: 1.4481x; 1.0511x over previous
#include <cuda_runtime.h>
#include <cuda_bf16.h>
#include <cstdint>

// Problem constants (fixed-shape problem)
#define T_DIM  128
#define B_DIM  2048
#define D_DIM  1024
#define AD_DIM 1024
#define KW     8
#define L_DIM  16
#define M_DIM  (L_DIM * B_DIM)   // 32768 gathered rows

// GEMM tiling (fp8 e4m3 mma.sync m16n8k32; sm_100 base target)
#define GBM   128                // M rows per unit
#define GBN   256                // N cols per unit
#define GBK   64                 // K elements per stage (64 fp8 = 64 B/row)
#define NPASS (AD_DIM / GBN)     // 4
#define NSTG  (D_DIM / GBK)      // 16
#define NBUF  3                  // pipeline depth

#define NUNITS ((M_DIM / GBM) * NPASS)   // 1024 work units (m_tile, nt)
#define GRID_GEMM 148                    // persistent CTAs (1 per SM)

#define ROWB    80               // padded row: 64 B data + 16 B pad
#define A_BYTES (GBM * ROWB)     // 10240
#define B_BYTES (GBN * ROWB)     // 20480
#define STG_BYTES (A_BYTES + B_BYTES)        // 30720
#define OFF_W2   0               // 256 floats
#define OFF_TILE 1024
#define GEMM_SMEM_TOTAL (OFF_TILE + NBUF * STG_BYTES)   // 93184

// ---------------------------------------------------------------------------
// Scratch (device globals: no allocations allowed in kernel_launch)
// ---------------------------------------------------------------------------
__device__ uint8_t g_blkB8[(size_t)M_DIM * D_DIM];   // 32 MiB gathered rows, e4m3
__device__ uint8_t g_W1b8[(size_t)AD_DIM * D_DIM];   // 1 MiB  W1 in e4m3
__device__ float   g_s[M_DIM];                       // s[m] = W2 . tanh(W1 blk_m)
__device__ float   g_p[M_DIM];                       // batch-softmax of s

// ---------------------------------------------------------------------------
// Helpers
// ---------------------------------------------------------------------------
__device__ __forceinline__ void window_of(int b, const int* __restrict__ off,
                                          const int* __restrict__ stc,
                                          const int* __restrict__ sep,
                                          int& start, int& end) {
    int o  = off[b];
    int sp = sep[b];          // sep_lst[b, 0]
    bool seg1 = (o <= sp);
    int s0 = o - KW;
    start = seg1 ? max(s0, 0) : max(s0, sp + 1);
    end   = seg1 ? min(o + KW, sp) : min(o + KW, stc[b]);
}

__device__ __forceinline__ uint32_t sptr(const void* p) {
    return (uint32_t)__cvta_generic_to_shared(p);
}
__device__ __forceinline__ void cp16(uint32_t dst, const void* src) {
    asm volatile("cp.async.cg.shared.global [%0], [%1], 16;" :: "r"(dst), "l"(src));
}
__device__ __forceinline__ void cp_commit() { asm volatile("cp.async.commit_group;"); }
template <int N> __device__ __forceinline__ void cp_wait() {
    asm volatile("cp.async.wait_group %0;" :: "n"(N));
}
__device__ __forceinline__ void ldsm4(uint32_t& r0, uint32_t& r1, uint32_t& r2, uint32_t& r3,
                                      uint32_t addr) {
    asm volatile("ldmatrix.sync.aligned.m8n8.x4.shared.b16 {%0,%1,%2,%3}, [%4];"
                 : "=r"(r0), "=r"(r1), "=r"(r2), "=r"(r3) : "r"(addr));
}
// fp8 e4m3 mma: m16n8k32, fragment layout = b16 m16n8k16 reinterpreted bytewise
__device__ __forceinline__ void mma16832(float* c, const uint32_t* a, uint32_t b0, uint32_t b1) {
    asm volatile(
        "mma.sync.aligned.m16n8k32.row.col.f32.e4m3.e4m3.f32 "
        "{%0,%1,%2,%3},{%4,%5,%6,%7},{%8,%9},{%0,%1,%2,%3};"
        : "+f"(c[0]), "+f"(c[1]), "+f"(c[2]), "+f"(c[3])
        : "r"(a[0]), "r"(a[1]), "r"(a[2]), "r"(a[3]), "r"(b0), "r"(b1));
}
// pack 2 floats -> e4m3x2 (lo = first/lower-k element)
__device__ __forceinline__ uint32_t fp8x2(float lo, float hi) {
    uint16_t p;
    asm("cvt.rn.satfinite.e4m3x2.f32 %0, %1, %2;" : "=h"(p) : "f"(hi), "f"(lo));
    return (uint32_t)p;
}
__device__ __forceinline__ float tanh_fast(float x) {
    float t;
    asm("tanh.approx.f32 %0, %1;" : "=f"(t) : "f"(x));
    return t;
}

// ---------------------------------------------------------------------------
// Kernel 1: W1 fp32 -> e4m3
// ---------------------------------------------------------------------------
__global__ void convert_w1_kernel(const float* __restrict__ W1) {
    int i = (blockIdx.x * blockDim.x + threadIdx.x) * 8;   // grid covers 1M elems
    float4 v0 = *(const float4*)(W1 + i);
    float4 v1 = *(const float4*)(W1 + i + 4);
    uint32_t p0 = fp8x2(v0.x, v0.y), p1 = fp8x2(v0.z, v0.w);
    uint32_t p2 = fp8x2(v1.x, v1.y), p3 = fp8x2(v1.z, v1.w);
    uint64_t o = (uint64_t)(p0 | (p1 << 16)) | ((uint64_t)(p2 | (p3 << 16)) << 32);
    *(uint64_t*)&g_W1b8[i] = o;
}

// ---------------------------------------------------------------------------
// Kernel 2: gather window rows -> e4m3 blk  (m = l*B + b); also zeros g_s[m]
// Invalid rows use a clipped index; their s is masked later and their final
// weight is exactly 0, so the garbage never propagates.
// ---------------------------------------------------------------------------
__global__ void gather_kernel(const float* __restrict__ h,
                              const int* __restrict__ off,
                              const int* __restrict__ stc,
                              const int* __restrict__ sep) {
    int m = blockIdx.x;
    if (threadIdx.x == 0) g_s[m] = 0.0f;    // GEMM accumulates into g_s
    int b = m & (B_DIM - 1);
    int l = m >> 11;
    int start, end;
    window_of(b, off, stc, sep, start, end);
    int idx = start + l;
    idx = min(max(idx, 0), T_DIM - 1);

    const float4* src = (const float4*)(h + ((size_t)idx * B_DIM + b) * D_DIM);
    int t = threadIdx.x;                    // 128 threads, 8 floats each
    float4 v0 = src[t * 2];
    float4 v1 = src[t * 2 + 1];
    uint32_t p0 = fp8x2(v0.x, v0.y), p1 = fp8x2(v0.z, v0.w);
    uint32_t p2 = fp8x2(v1.x, v1.y), p3 = fp8x2(v1.z, v1.w);
    uint64_t o = (uint64_t)(p0 | (p1 << 16)) | ((uint64_t)(p2 | (p3 << 16)) << 32);
    *(uint64_t*)&g_blkB8[(size_t)m * D_DIM + t * 8] = o;
}

// ---------------------------------------------------------------------------
// Kernel 3: persistent GEMM  pre[m,a] = blk[m,:] . W1[a,:]  (e4m3 -> fp32)
// fused epilogue: g_s[m] += sum_a W2[a] * tanh(pre[m,a])  (global red.add)
// 148 persistent CTAs x 512 threads; static partition of 1024 (m_tile, nt)
// units: u = cta, cta+148, ...
// ---------------------------------------------------------------------------
extern __shared__ char dyn_smem[];

__device__ __forceinline__ void load_stage(uint32_t tile_base, int slot, int k0,
                                           int m_base, int nbase, int tid) {
    uint32_t abase = tile_base + slot * STG_BYTES;
    uint32_t bbase = abase + A_BYTES;
    // A: 128 rows x 4 x16B chunks = 512 chunks, 1 per thread
    {
        int row = tid >> 2, c = tid & 3;
        cp16(abase + row * ROWB + c * 16,
             &g_blkB8[(size_t)(m_base + row) * D_DIM + k0 + c * 16]);
    }
    // B: 256 rows x 4 chunks = 1024 chunks, 2 per thread
    #pragma unroll
    for (int i = 0; i < 2; ++i) {
        int ch  = tid + i * 512;
        int row = ch >> 2, c = ch & 3;
        cp16(bbase + row * ROWB + c * 16,
             &g_W1b8[(size_t)(nbase + row) * D_DIM + k0 + c * 16]);
    }
}

__global__ void __launch_bounds__(512, 1) gemm_s_kernel(const float* __restrict__ W2) {
    const uint32_t smem_base = sptr(dyn_smem);
    const uint32_t tile_base = smem_base + OFF_TILE;
    float* sW2 = (float*)(dyn_smem + OFF_W2);

    const int tid  = threadIdx.x;
    const int wid  = tid >> 5;
    const int lane = tid & 31;

    const int warp_m = wid & 3;          // 4 -> 32 rows each
    const int warp_n = wid >> 2;         // 4 -> 64 cols each
    const int rm = warp_m * 32;
    const int cn = warp_n * 64;

    // ldmatrix lane geometry (verified)
    const int mat = lane >> 3;
    const int lq  = lane & 7;
    const int rowA0    = rm + (mat & 1) * 8 + lq;       // + fm*16
    const int colAbase = (mat >> 1) * 8;                // b16 units; + ks*16
    const int colBbase = (mat & 1) * 8;                 // b16 units; + ks*16

    for (int u = blockIdx.x; u < NUNITS; u += GRID_GEMM) {
        const int m_base = (u >> 2) * GBM;
        const int nbase  = (u & 3) * GBN;

        __syncthreads();                 // prev unit done with tiles/sW2
        if (tid < GBN) sW2[tid] = W2[nbase + tid];

        float acc[2][8][4];
        #pragma unroll
        for (int fm = 0; fm < 2; fm++)
            #pragma unroll
            for (int j = 0; j < 8; j++)
                #pragma unroll
                for (int r = 0; r < 4; r++) acc[fm][j][r] = 0.0f;

        // prologue: stages 0,1
        load_stage(tile_base, 0, 0, m_base, nbase, tid);
        cp_commit();
        load_stage(tile_base, 1, GBK, m_base, nbase, tid);
        cp_commit();

        int slot = 0;        // compute slot (s % 3)
        int lslot = 2;       // load slot ((s+2) % 3)
        for (int s = 0; s < NSTG; ++s) {
            if (s == NSTG - 1) { cp_wait<0>(); } else { cp_wait<1>(); }
            __syncthreads();             // stage s visible; all done with s-1
            if (s + 2 < NSTG) {
                load_stage(tile_base, lslot, (s + 2) * GBK, m_base, nbase, tid);
                cp_commit();
            }

            const uint32_t abase = tile_base + slot * STG_BYTES;
            const uint32_t bbase = abase + A_BYTES;
            #pragma unroll
            for (int ks = 0; ks < 2; ks++) {     // 2 x k32 per 64-elem stage
                uint32_t a[2][4];
                #pragma unroll
                for (int fm = 0; fm < 2; fm++)
                    ldsm4(a[fm][0], a[fm][1], a[fm][2], a[fm][3],
                          abase + (rowA0 + fm * 16) * ROWB + (colAbase + ks * 16) * 2);
                uint32_t bf[8][2];
                #pragma unroll
                for (int jp = 0; jp < 4; jp++) {
                    uint32_t b0, b1, b2, b3;
                    int rowB = cn + 8 * (2 * jp + (mat >> 1)) + lq;
                    ldsm4(b0, b1, b2, b3,
                          bbase + rowB * ROWB + (colBbase + ks * 16) * 2);
                    bf[2 * jp][0] = b0;  bf[2 * jp][1] = b1;
                    bf[2 * jp + 1][0] = b2;  bf[2 * jp + 1][1] = b3;
                }
                #pragma unroll
                for (int fm = 0; fm < 2; fm++)
                    #pragma unroll
                    for (int j = 0; j < 8; j++)
                        mma16832(acc[fm][j], a[fm], bf[j][0], bf[j][1]);
            }
            if (++slot == NBUF) slot = 0;
            if (++lslot == NBUF) lslot = 0;
        }

        // epilogue: g_s[row] += W2[a] * tanh(acc)  (global red.add)
        float p[4] = {0.f, 0.f, 0.f, 0.f};
        #pragma unroll
        for (int fm = 0; fm < 2; fm++)
            #pragma unroll
            for (int j = 0; j < 8; j++)
                #pragma unroll
                for (int r = 0; r < 4; r++) {
                    int col_local = cn + 8 * j + 2 * (lane & 3) + (r & 1);
                    p[fm * 2 + (r >> 1)] += sW2[col_local] * tanh_fast(acc[fm][j][r]);
                }
        #pragma unroll
        for (int i = 0; i < 4; i++) {
            p[i] += __shfl_xor_sync(0xffffffff, p[i], 1);
            p[i] += __shfl_xor_sync(0xffffffff, p[i], 2);
        }
        if ((lane & 3) == 0) {
            int r0 = m_base + rm + (lane >> 2);
            atomicAdd(&g_s[r0],      p[0]);
            atomicAdd(&g_s[r0 + 8],  p[1]);
            atomicAdd(&g_s[r0 + 16], p[2]);
            atomicAdd(&g_s[r0 + 24], p[3]);
        }
    }
}

// ---------------------------------------------------------------------------
// Kernel 4: softmax over batch axis per l; invalid entries use s = 0
// (matches reference: blk=0 for invalid -> s = W2.tanh(0) = 0)
// ---------------------------------------------------------------------------
__global__ void softmax_b_kernel(const int* __restrict__ off,
                                 const int* __restrict__ stc,
                                 const int* __restrict__ sep) {
    const int l = blockIdx.x;
    const int tid = threadIdx.x;                  // 256 threads, 8 b's each
    __shared__ float red[256];

    float v[8];
    float mx = -1e30f;
    #pragma unroll
    for (int i = 0; i < 8; i++) {
        int b = tid + i * 256;
        int start, end;
        window_of(b, off, stc, sep, start, end);
        bool valid = (start + l) < end;
        v[i] = valid ? g_s[l * B_DIM + b] : 0.0f;
        mx = fmaxf(mx, v[i]);
    }
    red[tid] = mx; __syncthreads();
    for (int s = 128; s > 0; s >>= 1) {
        if (tid < s) red[tid] = fmaxf(red[tid], red[tid + s]);
        __syncthreads();
    }
    mx = red[0]; __syncthreads();

    float e[8]; float sum = 0.0f;
    #pragma unroll
    for (int i = 0; i < 8; i++) { e[i] = expf(v[i] - mx); sum += e[i]; }
    red[tid] = sum; __syncthreads();
    for (int s = 128; s > 0; s >>= 1) {
        if (tid < s) red[tid] += red[tid + s];
        __syncthreads();
    }
    sum = red[0];

    float inv = 1.0f / sum;
    #pragma unroll
    for (int i = 0; i < 8; i++) {
        int b = tid + i * 256;
        g_p[l * B_DIM + b] = e[i] * inv;
    }
}

// ---------------------------------------------------------------------------
// Kernel 5: per-b masked softmax over L + fp32 weighted sum of h_context rows.
// grid (B, 2): each block covers 512 columns (one float4 slot per thread).
// All 16 l-steps run unconditionally (clipped idx, zero weight when invalid)
// -> 16 independent loads per thread, full MLP.
// ---------------------------------------------------------------------------
__global__ void finalize_kernel(const float* __restrict__ h,
                                const int* __restrict__ off,
                                const int* __restrict__ stc,
                                const int* __restrict__ sep,
                                float* __restrict__ out) {
    const int b = blockIdx.x;
    int start, end;
    window_of(b, off, stc, sep, start, end);

    float logit[L_DIM];
    float mx = -INFINITY;
    #pragma unroll
    for (int l = 0; l < L_DIM; l++) {
        bool valid = (start + l) < end;
        logit[l] = valid ? g_p[l * B_DIM + b] : -INFINITY;
        mx = fmaxf(mx, logit[l]);
    }
    float w[L_DIM]; float sum = 0.0f;
    #pragma unroll
    for (int l = 0; l < L_DIM; l++) { w[l] = expf(logit[l] - mx); sum += w[l]; }
    float inv = 1.0f / sum;

    const int col4 = blockIdx.y * 128 + threadIdx.x;   // float4 slot (0..255)
    float4 a = make_float4(0.f, 0.f, 0.f, 0.f);
    #pragma unroll
    for (int l = 0; l < L_DIM; l++) {
        int idx = min(max(start + l, 0), T_DIM - 1);
        float wl = (start + l < end) ? w[l] * inv : 0.0f;
        float4 x = ((const float4*)(h + ((size_t)idx * B_DIM + b) * D_DIM))[col4];
        a.x += wl * x.x; a.y += wl * x.y; a.z += wl * x.z; a.w += wl * x.w;
    }
    ((float4*)(out + (size_t)b * D_DIM))[col4] = a;
}

// ---------------------------------------------------------------------------
// Launch
// inputs (metadata order): h_context f32, offsets i32, stc_lens i32,
// sep_lst i32, no_local i32 (unused), W1 f32, W2 f32 -> out f32 (B,1,D)
// ---------------------------------------------------------------------------
extern "C" void kernel_launch(void* const* d_in, const int* in_sizes, int n_in,
                              void* d_out, int out_size) {
    (void)in_sizes; (void)n_in; (void)out_size;
    const float* h   = (const float*)d_in[0];
    const int*   off = (const int*)d_in[1];
    const int*   stc = (const int*)d_in[2];
    const int*   sep = (const int*)d_in[3];
    const float* W1  = (const float*)d_in[5];
    const float* W2  = (const float*)d_in[6];
    float*       out = (float*)d_out;

    static int smem_set = 0;
    if (!smem_set) {
        cudaFuncSetAttribute(gemm_s_kernel,
                             cudaFuncAttributeMaxDynamicSharedMemorySize, GEMM_SMEM_TOTAL);
        smem_set = 1;
    }

    convert_w1_kernel<<<(AD_DIM * D_DIM) / (256 * 8), 256>>>(W1);
    gather_kernel<<<M_DIM, 128>>>(h, off, stc, sep);
    gemm_s_kernel<<<GRID_GEMM, 512, GEMM_SMEM_TOTAL>>>(W2);
    softmax_b_kernel<<<L_DIM, 256>>>(off, stc, sep);
    finalize_kernel<<<dim3(B_DIM, 2), 128>>>(h, off, stc, sep, out);
}

// round 16
// speedup vs baseline: 1.4754x; 1.0188x over previous
#include <cuda_runtime.h>
#include <cuda_bf16.h>
#include <cstdint>

// Problem constants (fixed-shape problem)
#define T_DIM  128
#define B_DIM  2048
#define D_DIM  1024
#define AD_DIM 1024
#define KW     8
#define L_DIM  16
#define M_DIM  (L_DIM * B_DIM)   // 32768 gathered rows

// GEMM tiling (fp8 e4m3 mma.sync m16n8k32; sm_100 base target)
#define GBM   128                // M rows per unit
#define GBN   256                // N cols per unit
#define GBK   64                 // K elements per stage (64 fp8 = 64 B/row)
#define NPASS (AD_DIM / GBN)     // 4
#define NSTG  (D_DIM / GBK)      // 16
#define NBUF  3                  // pipeline depth

#define NUNITS ((M_DIM / GBM) * NPASS)   // 1024 work units (m_tile, nt)
#define GRID_GEMM 148                    // persistent CTAs (1 per SM)

#define ROWB    80               // padded row: 64 B data + 16 B pad
#define A_BYTES (GBM * ROWB)     // 10240
#define B_BYTES (GBN * ROWB)     // 20480
#define STG_BYTES (A_BYTES + B_BYTES)        // 30720
#define OFF_W2   0               // 256 floats
#define OFF_TILE 1024
#define GEMM_SMEM_TOTAL (OFF_TILE + NBUF * STG_BYTES)   // 93184

// merged gather+convert grid split
#define GATHER_BLOCKS  M_DIM                 // 32768 gather blocks
#define CONVERT_BLOCKS ((AD_DIM * D_DIM) / (128 * 8))   // 1024 convert blocks

// ---------------------------------------------------------------------------
// Scratch (device globals: no allocations allowed in kernel_launch)
// ---------------------------------------------------------------------------
__device__ uint8_t g_blkB8[(size_t)M_DIM * D_DIM];   // 32 MiB gathered rows, e4m3
__device__ uint8_t g_W1b8[(size_t)AD_DIM * D_DIM];   // 1 MiB  W1 in e4m3
__device__ float   g_s[M_DIM];                       // s[m] = W2 . tanh(W1 blk_m)
__device__ float   g_p[M_DIM];                       // batch-softmax of s

// ---------------------------------------------------------------------------
// Helpers
// ---------------------------------------------------------------------------
__device__ __forceinline__ void window_of(int b, const int* __restrict__ off,
                                          const int* __restrict__ stc,
                                          const int* __restrict__ sep,
                                          int& start, int& end) {
    int o  = off[b];
    int sp = sep[b];          // sep_lst[b, 0]
    bool seg1 = (o <= sp);
    int s0 = o - KW;
    start = seg1 ? max(s0, 0) : max(s0, sp + 1);
    end   = seg1 ? min(o + KW, sp) : min(o + KW, stc[b]);
}

__device__ __forceinline__ uint32_t sptr(const void* p) {
    return (uint32_t)__cvta_generic_to_shared(p);
}
__device__ __forceinline__ void cp16(uint32_t dst, const void* src) {
    asm volatile("cp.async.cg.shared.global [%0], [%1], 16;" :: "r"(dst), "l"(src));
}
__device__ __forceinline__ void cp_commit() { asm volatile("cp.async.commit_group;"); }
template <int N> __device__ __forceinline__ void cp_wait() {
    asm volatile("cp.async.wait_group %0;" :: "n"(N));
}
__device__ __forceinline__ void ldsm4(uint32_t& r0, uint32_t& r1, uint32_t& r2, uint32_t& r3,
                                      uint32_t addr) {
    asm volatile("ldmatrix.sync.aligned.m8n8.x4.shared.b16 {%0,%1,%2,%3}, [%4];"
                 : "=r"(r0), "=r"(r1), "=r"(r2), "=r"(r3) : "r"(addr));
}
// fp8 e4m3 mma: m16n8k32, fragment layout = b16 m16n8k16 reinterpreted bytewise
__device__ __forceinline__ void mma16832(float* c, const uint32_t* a, uint32_t b0, uint32_t b1) {
    asm volatile(
        "mma.sync.aligned.m16n8k32.row.col.f32.e4m3.e4m3.f32 "
        "{%0,%1,%2,%3},{%4,%5,%6,%7},{%8,%9},{%0,%1,%2,%3};"
        : "+f"(c[0]), "+f"(c[1]), "+f"(c[2]), "+f"(c[3])
        : "r"(a[0]), "r"(a[1]), "r"(a[2]), "r"(a[3]), "r"(b0), "r"(b1));
}
// pack 2 floats -> e4m3x2 (lo = first/lower-k element)
__device__ __forceinline__ uint32_t fp8x2(float lo, float hi) {
    uint16_t p;
    asm("cvt.rn.satfinite.e4m3x2.f32 %0, %1, %2;" : "=h"(p) : "f"(hi), "f"(lo));
    return (uint32_t)p;
}
__device__ __forceinline__ float tanh_fast(float x) {
    float t;
    asm("tanh.approx.f32 %0, %1;" : "=f"(t) : "f"(x));
    return t;
}

// ---------------------------------------------------------------------------
// Kernel 1 (merged): gather window rows -> e4m3 blk (blocks < M_DIM) and
// W1 fp32 -> e4m3 (blocks >= M_DIM). Also zeros g_s[m] in gather blocks.
// Invalid rows use a clipped index; their s is masked later and their final
// weight is exactly 0, so the garbage never propagates.
// ---------------------------------------------------------------------------
__global__ void gather_convert_kernel(const float* __restrict__ h,
                                      const int* __restrict__ off,
                                      const int* __restrict__ stc,
                                      const int* __restrict__ sep,
                                      const float* __restrict__ W1) {
    int t = threadIdx.x;                    // 128 threads
    if (blockIdx.x >= GATHER_BLOCKS) {
        // W1 convert block: 128 threads x 8 elems
        int w = blockIdx.x - GATHER_BLOCKS;
        int i = (w * 128 + t) * 8;
        float4 v0 = *(const float4*)(W1 + i);
        float4 v1 = *(const float4*)(W1 + i + 4);
        uint32_t p0 = fp8x2(v0.x, v0.y), p1 = fp8x2(v0.z, v0.w);
        uint32_t p2 = fp8x2(v1.x, v1.y), p3 = fp8x2(v1.z, v1.w);
        uint64_t o = (uint64_t)(p0 | (p1 << 16)) | ((uint64_t)(p2 | (p3 << 16)) << 32);
        *(uint64_t*)&g_W1b8[i] = o;
        return;
    }

    int m = blockIdx.x;
    if (t == 0) g_s[m] = 0.0f;              // GEMM accumulates into g_s
    int b = m & (B_DIM - 1);
    int l = m >> 11;
    int start, end;
    window_of(b, off, stc, sep, start, end);
    int idx = start + l;
    idx = min(max(idx, 0), T_DIM - 1);

    const float4* src = (const float4*)(h + ((size_t)idx * B_DIM + b) * D_DIM);
    float4 v0 = src[t * 2];
    float4 v1 = src[t * 2 + 1];
    uint32_t p0 = fp8x2(v0.x, v0.y), p1 = fp8x2(v0.z, v0.w);
    uint32_t p2 = fp8x2(v1.x, v1.y), p3 = fp8x2(v1.z, v1.w);
    uint64_t o = (uint64_t)(p0 | (p1 << 16)) | ((uint64_t)(p2 | (p3 << 16)) << 32);
    *(uint64_t*)&g_blkB8[(size_t)m * D_DIM + t * 8] = o;
}

// ---------------------------------------------------------------------------
// Kernel 2: persistent GEMM  pre[m,a] = blk[m,:] . W1[a,:]  (e4m3 -> fp32)
// fused epilogue: g_s[m] += sum_a W2[a] * tanh(pre[m,a])  (global red.add)
// 148 persistent CTAs x 512 threads; static partition of 1024 (m_tile, nt)
// units: u = cta, cta+148, ...
// ---------------------------------------------------------------------------
extern __shared__ char dyn_smem[];

__device__ __forceinline__ void load_stage(uint32_t tile_base, int slot, int k0,
                                           int m_base, int nbase, int tid) {
    uint32_t abase = tile_base + slot * STG_BYTES;
    uint32_t bbase = abase + A_BYTES;
    // A: 128 rows x 4 x16B chunks = 512 chunks, 1 per thread
    {
        int row = tid >> 2, c = tid & 3;
        cp16(abase + row * ROWB + c * 16,
             &g_blkB8[(size_t)(m_base + row) * D_DIM + k0 + c * 16]);
    }
    // B: 256 rows x 4 chunks = 1024 chunks, 2 per thread
    #pragma unroll
    for (int i = 0; i < 2; ++i) {
        int ch  = tid + i * 512;
        int row = ch >> 2, c = ch & 3;
        cp16(bbase + row * ROWB + c * 16,
             &g_W1b8[(size_t)(nbase + row) * D_DIM + k0 + c * 16]);
    }
}

__global__ void __launch_bounds__(512, 1) gemm_s_kernel(const float* __restrict__ W2) {
    const uint32_t smem_base = sptr(dyn_smem);
    const uint32_t tile_base = smem_base + OFF_TILE;
    float* sW2 = (float*)(dyn_smem + OFF_W2);

    const int tid  = threadIdx.x;
    const int wid  = tid >> 5;
    const int lane = tid & 31;

    const int warp_m = wid & 3;          // 4 -> 32 rows each
    const int warp_n = wid >> 2;         // 4 -> 64 cols each
    const int rm = warp_m * 32;
    const int cn = warp_n * 64;

    // ldmatrix lane geometry (verified)
    const int mat = lane >> 3;
    const int lq  = lane & 7;
    const int rowA0    = rm + (mat & 1) * 8 + lq;       // + fm*16
    const int colAbase = (mat >> 1) * 8;                // b16 units; + ks*16
    const int colBbase = (mat & 1) * 8;                 // b16 units; + ks*16

    for (int u = blockIdx.x; u < NUNITS; u += GRID_GEMM) {
        const int m_base = (u >> 2) * GBM;
        const int nbase  = (u & 3) * GBN;

        __syncthreads();                 // prev unit done with tiles/sW2
        if (tid < GBN) sW2[tid] = W2[nbase + tid];

        float acc[2][8][4];
        #pragma unroll
        for (int fm = 0; fm < 2; fm++)
            #pragma unroll
            for (int j = 0; j < 8; j++)
                #pragma unroll
                for (int r = 0; r < 4; r++) acc[fm][j][r] = 0.0f;

        // prologue: stages 0,1
        load_stage(tile_base, 0, 0, m_base, nbase, tid);
        cp_commit();
        load_stage(tile_base, 1, GBK, m_base, nbase, tid);
        cp_commit();

        int slot = 0;        // compute slot (s % 3)
        int lslot = 2;       // load slot ((s+2) % 3)
        for (int s = 0; s < NSTG; ++s) {
            if (s == NSTG - 1) { cp_wait<0>(); } else { cp_wait<1>(); }
            __syncthreads();             // stage s visible; all done with s-1
            if (s + 2 < NSTG) {
                load_stage(tile_base, lslot, (s + 2) * GBK, m_base, nbase, tid);
                cp_commit();
            }

            const uint32_t abase = tile_base + slot * STG_BYTES;
            const uint32_t bbase = abase + A_BYTES;
            #pragma unroll
            for (int ks = 0; ks < 2; ks++) {     // 2 x k32 per 64-elem stage
                uint32_t a[2][4];
                #pragma unroll
                for (int fm = 0; fm < 2; fm++)
                    ldsm4(a[fm][0], a[fm][1], a[fm][2], a[fm][3],
                          abase + (rowA0 + fm * 16) * ROWB + (colAbase + ks * 16) * 2);
                uint32_t bf[8][2];
                #pragma unroll
                for (int jp = 0; jp < 4; jp++) {
                    uint32_t b0, b1, b2, b3;
                    int rowB = cn + 8 * (2 * jp + (mat >> 1)) + lq;
                    ldsm4(b0, b1, b2, b3,
                          bbase + rowB * ROWB + (colBbase + ks * 16) * 2);
                    bf[2 * jp][0] = b0;  bf[2 * jp][1] = b1;
                    bf[2 * jp + 1][0] = b2;  bf[2 * jp + 1][1] = b3;
                }
                #pragma unroll
                for (int fm = 0; fm < 2; fm++)
                    #pragma unroll
                    for (int j = 0; j < 8; j++)
                        mma16832(acc[fm][j], a[fm], bf[j][0], bf[j][1]);
            }
            if (++slot == NBUF) slot = 0;
            if (++lslot == NBUF) lslot = 0;
        }

        // epilogue: g_s[row] += W2[a] * tanh(acc)  (global red.add)
        float p[4] = {0.f, 0.f, 0.f, 0.f};
        #pragma unroll
        for (int fm = 0; fm < 2; fm++)
            #pragma unroll
            for (int j = 0; j < 8; j++)
                #pragma unroll
                for (int r = 0; r < 4; r++) {
                    int col_local = cn + 8 * j + 2 * (lane & 3) + (r & 1);
                    p[fm * 2 + (r >> 1)] += sW2[col_local] * tanh_fast(acc[fm][j][r]);
                }
        #pragma unroll
        for (int i = 0; i < 4; i++) {
            p[i] += __shfl_xor_sync(0xffffffff, p[i], 1);
            p[i] += __shfl_xor_sync(0xffffffff, p[i], 2);
        }
        if ((lane & 3) == 0) {
            int r0 = m_base + rm + (lane >> 2);
            atomicAdd(&g_s[r0],      p[0]);
            atomicAdd(&g_s[r0 + 8],  p[1]);
            atomicAdd(&g_s[r0 + 16], p[2]);
            atomicAdd(&g_s[r0 + 24], p[3]);
        }
    }
}

// ---------------------------------------------------------------------------
// Kernel 3: softmax over batch axis per l; invalid entries use s = 0
// (matches reference: blk=0 for invalid -> s = W2.tanh(0) = 0)
// ---------------------------------------------------------------------------
__global__ void softmax_b_kernel(const int* __restrict__ off,
                                 const int* __restrict__ stc,
                                 const int* __restrict__ sep) {
    const int l = blockIdx.x;
    const int tid = threadIdx.x;                  // 256 threads, 8 b's each
    __shared__ float red[256];

    float v[8];
    float mx = -1e30f;
    #pragma unroll
    for (int i = 0; i < 8; i++) {
        int b = tid + i * 256;
        int start, end;
        window_of(b, off, stc, sep, start, end);
        bool valid = (start + l) < end;
        v[i] = valid ? g_s[l * B_DIM + b] : 0.0f;
        mx = fmaxf(mx, v[i]);
    }
    red[tid] = mx; __syncthreads();
    for (int s = 128; s > 0; s >>= 1) {
        if (tid < s) red[tid] = fmaxf(red[tid], red[tid + s]);
        __syncthreads();
    }
    mx = red[0]; __syncthreads();

    float e[8]; float sum = 0.0f;
    #pragma unroll
    for (int i = 0; i < 8; i++) { e[i] = expf(v[i] - mx); sum += e[i]; }
    red[tid] = sum; __syncthreads();
    for (int s = 128; s > 0; s >>= 1) {
        if (tid < s) red[tid] += red[tid + s];
        __syncthreads();
    }
    sum = red[0];

    float inv = 1.0f / sum;
    #pragma unroll
    for (int i = 0; i < 8; i++) {
        int b = tid + i * 256;
        g_p[l * B_DIM + b] = e[i] * inv;
    }
}

// ---------------------------------------------------------------------------
// Kernel 4: per-b masked softmax over L + fp32 weighted sum of h_context rows.
// grid (B, 2): each block covers 512 columns (one float4 slot per thread).
// All 16 l-steps run unconditionally (clipped idx, zero weight when invalid)
// -> 16 independent loads per thread, full MLP.
// ---------------------------------------------------------------------------
__global__ void finalize_kernel(const float* __restrict__ h,
                                const int* __restrict__ off,
                                const int* __restrict__ stc,
                                const int* __restrict__ sep,
                                float* __restrict__ out) {
    const int b = blockIdx.x;
    int start, end;
    window_of(b, off, stc, sep, start, end);

    float logit[L_DIM];
    float mx = -INFINITY;
    #pragma unroll
    for (int l = 0; l < L_DIM; l++) {
        bool valid = (start + l) < end;
        logit[l] = valid ? g_p[l * B_DIM + b] : -INFINITY;
        mx = fmaxf(mx, logit[l]);
    }
    float w[L_DIM]; float sum = 0.0f;
    #pragma unroll
    for (int l = 0; l < L_DIM; l++) { w[l] = expf(logit[l] - mx); sum += w[l]; }
    float inv = 1.0f / sum;

    const int col4 = blockIdx.y * 128 + threadIdx.x;   // float4 slot (0..255)
    float4 a = make_float4(0.f, 0.f, 0.f, 0.f);
    #pragma unroll
    for (int l = 0; l < L_DIM; l++) {
        int idx = min(max(start + l, 0), T_DIM - 1);
        float wl = (start + l < end) ? w[l] * inv : 0.0f;
        float4 x = ((const float4*)(h + ((size_t)idx * B_DIM + b) * D_DIM))[col4];
        a.x += wl * x.x; a.y += wl * x.y; a.z += wl * x.z; a.w += wl * x.w;
    }
    ((float4*)(out + (size_t)b * D_DIM))[col4] = a;
}

// ---------------------------------------------------------------------------
// Launch
// inputs (metadata order): h_context f32, offsets i32, stc_lens i32,
// sep_lst i32, no_local i32 (unused), W1 f32, W2 f32 -> out f32 (B,1,D)
// ---------------------------------------------------------------------------
extern "C" void kernel_launch(void* const* d_in, const int* in_sizes, int n_in,
                              void* d_out, int out_size) {
    (void)in_sizes; (void)n_in; (void)out_size;
    const float* h   = (const float*)d_in[0];
    const int*   off = (const int*)d_in[1];
    const int*   stc = (const int*)d_in[2];
    const int*   sep = (const int*)d_in[3];
    const float* W1  = (const float*)d_in[5];
    const float* W2  = (const float*)d_in[6];
    float*       out = (float*)d_out;

    static int smem_set = 0;
    if (!smem_set) {
        cudaFuncSetAttribute(gemm_s_kernel,
                             cudaFuncAttributeMaxDynamicSharedMemorySize, GEMM_SMEM_TOTAL);
        smem_set = 1;
    }

    gather_convert_kernel<<<GATHER_BLOCKS + CONVERT_BLOCKS, 128>>>(h, off, stc, sep, W1);
    gemm_s_kernel<<<GRID_GEMM, 512, GEMM_SMEM_TOTAL>>>(W2);
    softmax_b_kernel<<<L_DIM, 256>>>(off, stc, sep);
    finalize_kernel<<<dim3(B_DIM, 2), 128>>>(h, off, stc, sep, out);
}